// round 5
// baseline (speedup 1.0000x reference)
#include <cuda_runtime.h>
#include <cstdint>

// ---------------------------------------------------------------------------
// HGCNLayer: two-hop mean aggregation over a bipartite graph.
//   rst  = segsum(h_src[edge_src] -> edge_dst) / max(deg_dst,1)
//   bsrc = segsum(rst[edge_dst]   -> edge_src) / max(deg_src,1)   (NORM_2=-1)
// Output layout: [bsrc (n_src x 128) | rst (n_dst x 128)]
//
// CSR built on the fly per direction; the dir-1 build is forked onto a second
// stream so it overlaps the dir-0 build + forward gather. Gathers are
// warp-per-node float4 sums (no float atomics), fused degree scale.
// ---------------------------------------------------------------------------

#define D_FEAT 128
#define MAXN   (1 << 21)
#define MAXE   (1 << 21)
#define SCAN_T 1024

// index 0 = dst-direction (group edges by dst, store src ids)
// index 1 = src-direction (group edges by src, store dst ids)
__device__ int g_cnt[2][MAXN];       // degree counts, then reused as fill cursors
__device__ int g_off[2][MAXN + 1];   // exclusive offsets
__device__ int g_csr[2][MAXE];       // neighbor ids
__device__ int g_bsum[2][2048];      // per-block partial sums for the scan

// --- zero the count prefix (one direction) ---
__global__ void zero_cnt_kernel(int which, int n) {
    int i = blockIdx.x * blockDim.x + threadIdx.x;
    if (i < n) g_cnt[which][i] = 0;
}

// --- degree counting (one direction) ---
__global__ void degree_kernel(int which, const int* __restrict__ key,
                              int n_edges) {
    int e = blockIdx.x * blockDim.x + threadIdx.x;
    if (e < n_edges) atomicAdd(&g_cnt[which][key[e]], 1);
}

// --- scan pass 1: per-block (1024-elem) sums ---
__global__ void scan_pass1(int which, int n) {
    __shared__ int sh[SCAN_T];
    int t = threadIdx.x;
    int i = blockIdx.x * SCAN_T + t;
    sh[t] = (i < n) ? g_cnt[which][i] : 0;
    __syncthreads();
    for (int s = SCAN_T / 2; s > 0; s >>= 1) {
        if (t < s) sh[t] += sh[t + s];
        __syncthreads();
    }
    if (t == 0) g_bsum[which][blockIdx.x] = sh[0];
}

// --- scan pass 2: exclusive scan of block sums (single block, one dir) ---
__global__ void scan_pass2(int which, int nb) {
    __shared__ int sh[SCAN_T];
    int t = threadIdx.x;
    int v = (t < nb) ? g_bsum[which][t] : 0;
    sh[t] = v;
    __syncthreads();
    for (int s = 1; s < SCAN_T; s <<= 1) {
        int u = (t >= s) ? sh[t - s] : 0;
        __syncthreads();
        sh[t] += u;
        __syncthreads();
    }
    if (t < nb) g_bsum[which][t] = sh[t] - v;   // exclusive
}

// --- scan pass 3: block-local exclusive scan + block offset; writes off+cursor ---
__global__ void scan_pass3(int which, int n) {
    __shared__ int sh[SCAN_T];
    int t = threadIdx.x;
    int i = blockIdx.x * SCAN_T + t;
    int v = (i < n) ? g_cnt[which][i] : 0;
    sh[t] = v;
    __syncthreads();
    for (int s = 1; s < SCAN_T; s <<= 1) {
        int u = (t >= s) ? sh[t - s] : 0;
        __syncthreads();
        sh[t] += u;
        __syncthreads();
    }
    if (i < n) {
        int ex = sh[t] - v + g_bsum[which][blockIdx.x];
        g_off[which][i] = ex;
        g_cnt[which][i] = ex;                   // fill cursor
        if (i == n - 1) g_off[which][n] = ex + v;
    }
}

// --- bucket fill (one direction): scatter neighbor ids into CSR order ---
__global__ void fill_kernel(int which, const int* __restrict__ key,
                            const int* __restrict__ val, int n_edges) {
    int e = blockIdx.x * blockDim.x + threadIdx.x;
    if (e < n_edges) {
        int p = atomicAdd(&g_cnt[which][key[e]], 1);
        g_csr[which][p] = val[e];
    }
}

// --- warp-per-node gather-sum with fused 1/max(deg,1) scale ---
__global__ void gather_kernel(int which,
                              const float* __restrict__ feat,
                              float*       __restrict__ out,
                              int n_nodes) {
    int gtid = blockIdx.x * blockDim.x + threadIdx.x;
    int w    = gtid >> 5;               // node id
    int lane = threadIdx.x & 31;
    if (w >= n_nodes) return;

    const int* off = g_off[which];
    const int* csr = g_csr[which];

    int beg = off[w];
    int end = off[w + 1];

    float4 acc = make_float4(0.f, 0.f, 0.f, 0.f);
    int j = beg;
    // unroll-8: 8 outstanding 512B row loads per warp (MLP for L2 latency)
    for (; j + 8 <= end; j += 8) {
        float4 r[8];
        #pragma unroll
        for (int k = 0; k < 8; k++) {
            int id = csr[j + k];
            r[k] = __ldg(reinterpret_cast<const float4*>(
                             feat + (size_t)id * D_FEAT) + lane);
        }
        #pragma unroll
        for (int k = 0; k < 8; k++) {
            acc.x += r[k].x; acc.y += r[k].y;
            acc.z += r[k].z; acc.w += r[k].w;
        }
    }
    for (; j + 4 <= end; j += 4) {
        float4 r[4];
        #pragma unroll
        for (int k = 0; k < 4; k++) {
            int id = csr[j + k];
            r[k] = __ldg(reinterpret_cast<const float4*>(
                             feat + (size_t)id * D_FEAT) + lane);
        }
        #pragma unroll
        for (int k = 0; k < 4; k++) {
            acc.x += r[k].x; acc.y += r[k].y;
            acc.z += r[k].z; acc.w += r[k].w;
        }
    }
    for (; j < end; j++) {
        float4 a = __ldg(reinterpret_cast<const float4*>(
                             feat + (size_t)csr[j] * D_FEAT) + lane);
        acc.x += a.x; acc.y += a.y; acc.z += a.z; acc.w += a.w;
    }

    int deg = end - beg;
    float inv = 1.0f / (float)(deg > 0 ? deg : 1);
    acc.x *= inv; acc.y *= inv; acc.z *= inv; acc.w *= inv;
    reinterpret_cast<float4*>(out + (size_t)w * D_FEAT)[lane] = acc;
}

extern "C" void kernel_launch(void* const* d_in, const int* in_sizes, int n_in,
                              void* d_out, int out_size) {
    const float* h_src    = (const float*)d_in[0];
    const int*   edge_src = (const int*)d_in[1];
    const int*   edge_dst = (const int*)d_in[2];

    const int n_src   = in_sizes[0] / D_FEAT;
    const int n_edges = in_sizes[1];
    const int n_dst   = out_size / D_FEAT - n_src;

    float* bsrc = (float*)d_out;                          // [n_src, 128]
    float* rst  = (float*)d_out + (size_t)n_src * D_FEAT; // [n_dst, 128]

    const int nb0 = (n_dst + SCAN_T - 1) / SCAN_T;
    const int nb1 = (n_src + SCAN_T - 1) / SCAN_T;
    const int EB  = (n_edges + 255) / 256;

    // Second stream for the dir-1 CSR build (overlaps dir-0 build + fwd gather).
    cudaStream_t s1;
    cudaStreamCreateWithFlags(&s1, cudaStreamNonBlocking);
    cudaEvent_t evFork, evJoin;
    cudaEventCreateWithFlags(&evFork, cudaEventDisableTiming);
    cudaEventCreateWithFlags(&evJoin, cudaEventDisableTiming);

    // fork
    cudaEventRecord(evFork, 0);
    cudaStreamWaitEvent(s1, evFork, 0);

    // --- stream s1: direction 1 (group by src, store dst) ---
    zero_cnt_kernel<<<(n_src + 255) / 256, 256, 0, s1>>>(1, n_src);
    degree_kernel<<<EB, 256, 0, s1>>>(1, edge_src, n_edges);
    scan_pass1<<<nb1, SCAN_T, 0, s1>>>(1, n_src);
    scan_pass2<<<1, SCAN_T, 0, s1>>>(1, nb1);
    scan_pass3<<<nb1, SCAN_T, 0, s1>>>(1, n_src);
    fill_kernel<<<EB, 256, 0, s1>>>(1, edge_src, edge_dst, n_edges);
    cudaEventRecord(evJoin, s1);

    // --- default stream: direction 0 build + forward gather ---
    zero_cnt_kernel<<<(n_dst + 255) / 256, 256>>>(0, n_dst);
    degree_kernel<<<EB, 256>>>(0, edge_dst, n_edges);
    scan_pass1<<<nb0, SCAN_T>>>(0, n_dst);
    scan_pass2<<<1, SCAN_T>>>(0, nb0);
    scan_pass3<<<nb0, SCAN_T>>>(0, n_dst);
    fill_kernel<<<EB, 256>>>(0, edge_dst, edge_src, n_edges);

    // forward: rst = mean over incoming src rows
    {
        long long thr = (long long)n_dst * 32;
        gather_kernel<<<(int)((thr + 255) / 256), 256>>>(0, h_src, rst, n_dst);
    }

    // join: backward gather needs dir-1 CSR
    cudaStreamWaitEvent(0, evJoin, 0);

    // backward: bsrc = mean over incoming rst rows (NORM_2 = -1)
    {
        long long thr = (long long)n_src * 32;
        gather_kernel<<<(int)((thr + 255) / 256), 256>>>(1, rst, bsrc, n_src);
    }

    cudaEventDestroy(evFork);
    cudaEventDestroy(evJoin);
    cudaStreamDestroy(s1);
}